// round 1
// baseline (speedup 1.0000x reference)
#include <cuda_runtime.h>
#include <math.h>

#define BB 2
#define SS 4096
#define DD 768
#define HH 12
#define DHD 64
#define NROW (BB*SS)

// Scratch for projected Q/K/V: [B,H,S,DH] each, fp32. 3 x 25.2 MB = 75 MB.
__device__ float g_q[(size_t)BB*HH*SS*DHD];
__device__ float g_k[(size_t)BB*HH*SS*DHD];
__device__ float g_v[(size_t)BB*HH*SS*DHD];

// ---------------------------------------------------------------------------
// QKV projection: for head h, out[n, e] = sum_d x[n, d] * W[h, d, e]
// Tile: 64 rows (n) x 64 cols (e = DH), K-chunk 32. 256 threads, 4x4 microtile
// per matrix (Q, K, V share the X tile).
// grid: (NROW/64, H), block: 256
// ---------------------------------------------------------------------------
__global__ __launch_bounds__(256, 4)
void qkv_proj_kernel(const float* __restrict__ x,
                     const float* __restrict__ Wq,
                     const float* __restrict__ Wk,
                     const float* __restrict__ Wv) {
    const int BM = 64, BK = 32;
    __shared__ __align__(16) float Xs[BM][BK];     // row stride 32: 2 distinct rows/warp -> broadcast, conflict-free
    __shared__ __align__(16) float Wqs[BK][DHD];
    __shared__ __align__(16) float Wks[BK][DHD];
    __shared__ __align__(16) float Wvs[BK][DHD];

    const int t  = threadIdx.x;
    const int h  = blockIdx.y;
    const int m0 = blockIdx.x * BM;
    const int ty = t >> 4;        // 0..15, 4 rows each
    const int tx = t & 15;        // 0..15, 4 cols each

    float aq[4][4] = {}, ak[4][4] = {}, av[4][4] = {};

    const float* wq = Wq + (size_t)h * DD * DHD;
    const float* wk = Wk + (size_t)h * DD * DHD;
    const float* wv = Wv + (size_t)h * DD * DHD;

    for (int k0 = 0; k0 < DD; k0 += BK) {
        // X tile: 64x32 = 512 float4, 2 per thread
        #pragma unroll
        for (int i = 0; i < 2; i++) {
            int idx = t + i * 256;          // float4 index
            int row = idx >> 3;             // 8 float4 per row
            int col = (idx & 7) * 4;
            *(float4*)&Xs[row][col] =
                *(const float4*)&x[(size_t)(m0 + row) * DD + k0 + col];
        }
        // W tiles: each K-chunk is a contiguous 32*64 block of W[h]
        #pragma unroll
        for (int i = 0; i < 2; i++) {
            int idx4 = (t + i * 256);       // float4 index within 512
            const float4* sq = (const float4*)(wq + (size_t)k0 * DHD);
            const float4* sk = (const float4*)(wk + (size_t)k0 * DHD);
            const float4* sv = (const float4*)(wv + (size_t)k0 * DHD);
            ((float4*)&Wqs[0][0])[idx4] = sq[idx4];
            ((float4*)&Wks[0][0])[idx4] = sk[idx4];
            ((float4*)&Wvs[0][0])[idx4] = sv[idx4];
        }
        __syncthreads();

        #pragma unroll
        for (int kk = 0; kk < BK; kk++) {
            float xa[4];
            #pragma unroll
            for (int i = 0; i < 4; i++) xa[i] = Xs[ty * 4 + i][kk];
            float4 bq = *(const float4*)&Wqs[kk][tx * 4];
            float4 bk = *(const float4*)&Wks[kk][tx * 4];
            float4 bv = *(const float4*)&Wvs[kk][tx * 4];
            #pragma unroll
            for (int i = 0; i < 4; i++) {
                aq[i][0] += xa[i] * bq.x; aq[i][1] += xa[i] * bq.y;
                aq[i][2] += xa[i] * bq.z; aq[i][3] += xa[i] * bq.w;
                ak[i][0] += xa[i] * bk.x; ak[i][1] += xa[i] * bk.y;
                ak[i][2] += xa[i] * bk.z; ak[i][3] += xa[i] * bk.w;
                av[i][0] += xa[i] * bv.x; av[i][1] += xa[i] * bv.y;
                av[i][2] += xa[i] * bv.z; av[i][3] += xa[i] * bv.w;
            }
        }
        __syncthreads();
    }

    const int b  = m0 / SS;
    const int s0 = m0 % SS;
    const size_t ob = ((size_t)(b * HH + h) * SS + s0) * DHD;
    #pragma unroll
    for (int i = 0; i < 4; i++) {
        size_t ro = ob + (size_t)(ty * 4 + i) * DHD + tx * 4;
        *(float4*)&g_q[ro] = make_float4(aq[i][0], aq[i][1], aq[i][2], aq[i][3]);
        *(float4*)&g_k[ro] = make_float4(ak[i][0], ak[i][1], ak[i][2], ak[i][3]);
        *(float4*)&g_v[ro] = make_float4(av[i][0], av[i][1], av[i][2], av[i][3]);
    }
}

// ---------------------------------------------------------------------------
// Flash attention (causal, fp32, online softmax).
// grid: (S/64, B*H), block: 128. Q tile = 64 rows, K/V tiles = 64 rows.
// Each thread: 4 q-rows x 8 dh-cols register accumulator.
// Dynamic smem: Qs/Ks/Vs/Ss [64][65] + m/l/scale[64].
// ---------------------------------------------------------------------------
#define PAD 65
#define ATT_SMEM_BYTES ((4 * 64 * PAD + 3 * 64) * sizeof(float))

__global__ __launch_bounds__(128, 3)
void flash_attn_kernel(float* __restrict__ out) {
    extern __shared__ float smem[];
    float* Qs = smem;                       // [64][PAD]
    float* Ks = Qs + 64 * PAD;
    float* Vs = Ks + 64 * PAD;
    float* Ss = Vs + 64 * PAD;
    float* m_s     = Ss + 64 * PAD;         // [64]
    float* l_s     = m_s + 64;
    float* scale_s = l_s + 64;

    const int t  = threadIdx.x;
    const int bh = blockIdx.y;              // b*H + h
    const int b  = bh / HH;
    const int h  = bh % HH;
    const int qi = blockIdx.x;
    const int q0 = qi * 64;

    const float* qp    = g_q + ((size_t)bh * SS + q0) * DHD;
    const float* kbase = g_k + (size_t)bh * SS * DHD;
    const float* vbase = g_v + (size_t)bh * SS * DHD;

    // Load Q tile: 64x64 floats = 1024 float4-equivalents; float4 global loads,
    // scalar smem stores (PAD=65 rows are not 16B aligned).
    #pragma unroll
    for (int i = 0; i < 8; i++) {
        int idx = t + i * 128;              // float4 index
        int row = idx >> 4;                 // 16 float4 per row
        int col = (idx & 15) * 4;
        float4 v = *(const float4*)&qp[(size_t)row * DHD + col];
        Qs[row * PAD + col + 0] = v.x;
        Qs[row * PAD + col + 1] = v.y;
        Qs[row * PAD + col + 2] = v.z;
        Qs[row * PAD + col + 3] = v.w;
    }
    if (t < 64) { m_s[t] = -INFINITY; l_s[t] = 0.0f; }

    const int rg = t >> 3;                  // 0..15 (4 rows each)
    const int cg = t & 7;                   // 0..7  (8 cols each)
    float acc[4][8] = {};

    for (int j = 0; j <= qi; j++) {
        __syncthreads();                    // prev iter done with Ks/Vs/Ss/scale_s
        const float* kp = kbase + (size_t)j * 64 * DHD;
        const float* vp = vbase + (size_t)j * 64 * DHD;
        #pragma unroll
        for (int i = 0; i < 8; i++) {
            int idx = t + i * 128;
            int row = idx >> 4;
            int col = (idx & 15) * 4;
            float4 kv = *(const float4*)&kp[(size_t)row * DHD + col];
            float4 vv = *(const float4*)&vp[(size_t)row * DHD + col];
            Ks[row * PAD + col + 0] = kv.x; Ks[row * PAD + col + 1] = kv.y;
            Ks[row * PAD + col + 2] = kv.z; Ks[row * PAD + col + 3] = kv.w;
            Vs[row * PAD + col + 0] = vv.x; Vs[row * PAD + col + 1] = vv.y;
            Vs[row * PAD + col + 2] = vv.z; Vs[row * PAD + col + 3] = vv.w;
        }
        __syncthreads();

        // S = Q K^T (per-thread 4x8 tile)
        float sc[4][8] = {};
        #pragma unroll
        for (int k = 0; k < DHD; k++) {
            float qv[4], kv[8];
            #pragma unroll
            for (int i = 0; i < 4; i++)  qv[i] = Qs[(rg * 4 + i) * PAD + k];
            #pragma unroll
            for (int jj = 0; jj < 8; jj++) kv[jj] = Ks[(cg * 8 + jj) * PAD + k];
            #pragma unroll
            for (int i = 0; i < 4; i++)
                #pragma unroll
                for (int jj = 0; jj < 8; jj++)
                    sc[i][jj] += qv[i] * kv[jj];
        }
        const float scale = 0.125f;          // 1/sqrt(64)
        const bool diag = (j == qi);
        #pragma unroll
        for (int i = 0; i < 4; i++) {
            int r = rg * 4 + i;
            #pragma unroll
            for (int jj = 0; jj < 8; jj++) {
                int c = cg * 8 + jj;
                float v = sc[i][jj] * scale;
                if (diag && c > r) v = -INFINITY;
                Ss[r * PAD + c] = v;
            }
        }
        __syncthreads();

        // Online softmax: one thread per row
        if (t < 64) {
            float mo = m_s[t];
            float mx = mo;
            #pragma unroll 8
            for (int c = 0; c < 64; c++) mx = fmaxf(mx, Ss[t * PAD + c]);
            float sr = __expf(mo - mx);     // 0 when mo = -inf (first tile)
            float l  = l_s[t] * sr;
            #pragma unroll 8
            for (int c = 0; c < 64; c++) {
                float p = __expf(Ss[t * PAD + c] - mx);
                Ss[t * PAD + c] = p;
                l += p;
            }
            m_s[t] = mx; l_s[t] = l; scale_s[t] = sr;
        }
        __syncthreads();

        // Rescale accumulators and O += P @ V
        float sr[4];
        #pragma unroll
        for (int i = 0; i < 4; i++) sr[i] = scale_s[rg * 4 + i];
        #pragma unroll
        for (int i = 0; i < 4; i++)
            #pragma unroll
            for (int jj = 0; jj < 8; jj++)
                acc[i][jj] *= sr[i];

        #pragma unroll
        for (int c = 0; c < 64; c++) {
            float pv[4], vv[8];
            #pragma unroll
            for (int i = 0; i < 4; i++)  pv[i] = Ss[(rg * 4 + i) * PAD + c];
            #pragma unroll
            for (int jj = 0; jj < 8; jj++) vv[jj] = Vs[c * PAD + cg * 8 + jj];
            #pragma unroll
            for (int i = 0; i < 4; i++)
                #pragma unroll
                for (int jj = 0; jj < 8; jj++)
                    acc[i][jj] += pv[i] * vv[jj];
        }
    }
    __syncthreads();

    // Write out[b][s][h*DH + e] = acc / l
    #pragma unroll
    for (int i = 0; i < 4; i++) {
        int r = rg * 4 + i;
        float linv = 1.0f / l_s[r];
        size_t o = ((size_t)b * SS + q0 + r) * (HH * DHD) + h * DHD + cg * 8;
        float4 v0 = make_float4(acc[i][0] * linv, acc[i][1] * linv,
                                acc[i][2] * linv, acc[i][3] * linv);
        float4 v1 = make_float4(acc[i][4] * linv, acc[i][5] * linv,
                                acc[i][6] * linv, acc[i][7] * linv);
        *(float4*)&out[o]     = v0;
        *(float4*)&out[o + 4] = v1;
    }
}

extern "C" void kernel_launch(void* const* d_in, const int* in_sizes, int n_in,
                              void* d_out, int out_size) {
    const float* x  = (const float*)d_in[0];
    const float* Wq = (const float*)d_in[1];
    const float* Wk = (const float*)d_in[2];
    const float* Wv = (const float*)d_in[3];
    float* out = (float*)d_out;

    cudaFuncSetAttribute(flash_attn_kernel,
                         cudaFuncAttributeMaxDynamicSharedMemorySize,
                         (int)ATT_SMEM_BYTES);

    qkv_proj_kernel<<<dim3(NROW / 64, HH), 256>>>(x, Wq, Wk, Wv);
    flash_attn_kernel<<<dim3(SS / 64, BB * HH), 128, ATT_SMEM_BYTES>>>(out);
}

// round 2
// speedup vs baseline: 1.3349x; 1.3349x over previous
#include <cuda_runtime.h>
#include <math.h>
#include <stdint.h>

#define BB 2
#define SS 4096
#define DD 768
#define HH 12
#define DHD 64
#define NROW (BB*SS)

// Scratch for projected Q/K/V: [B,H,S,DH] each, fp32.
__device__ float g_q[(size_t)BB*HH*SS*DHD];
__device__ float g_k[(size_t)BB*HH*SS*DHD];
__device__ float g_v[(size_t)BB*HH*SS*DHD];

// ---------------------------------------------------------------------------
// QKV projection (unchanged from R1): 64x64 tile per head, fp32 SIMT.
// ---------------------------------------------------------------------------
__global__ __launch_bounds__(256, 4)
void qkv_proj_kernel(const float* __restrict__ x,
                     const float* __restrict__ Wq,
                     const float* __restrict__ Wk,
                     const float* __restrict__ Wv) {
    const int BM = 64, BK = 32;
    __shared__ __align__(16) float Xs[BM][BK];
    __shared__ __align__(16) float Wqs[BK][DHD];
    __shared__ __align__(16) float Wks[BK][DHD];
    __shared__ __align__(16) float Wvs[BK][DHD];

    const int t  = threadIdx.x;
    const int h  = blockIdx.y;
    const int m0 = blockIdx.x * BM;
    const int ty = t >> 4;
    const int tx = t & 15;

    float aq[4][4] = {}, ak[4][4] = {}, av[4][4] = {};

    const float* wq = Wq + (size_t)h * DD * DHD;
    const float* wk = Wk + (size_t)h * DD * DHD;
    const float* wv = Wv + (size_t)h * DD * DHD;

    for (int k0 = 0; k0 < DD; k0 += BK) {
        #pragma unroll
        for (int i = 0; i < 2; i++) {
            int idx = t + i * 256;
            int row = idx >> 3;
            int col = (idx & 7) * 4;
            *(float4*)&Xs[row][col] =
                *(const float4*)&x[(size_t)(m0 + row) * DD + k0 + col];
        }
        #pragma unroll
        for (int i = 0; i < 2; i++) {
            int idx4 = (t + i * 256);
            const float4* sq = (const float4*)(wq + (size_t)k0 * DHD);
            const float4* sk = (const float4*)(wk + (size_t)k0 * DHD);
            const float4* sv = (const float4*)(wv + (size_t)k0 * DHD);
            ((float4*)&Wqs[0][0])[idx4] = sq[idx4];
            ((float4*)&Wks[0][0])[idx4] = sk[idx4];
            ((float4*)&Wvs[0][0])[idx4] = sv[idx4];
        }
        __syncthreads();

        #pragma unroll
        for (int kk = 0; kk < BK; kk++) {
            float xa[4];
            #pragma unroll
            for (int i = 0; i < 4; i++) xa[i] = Xs[ty * 4 + i][kk];
            float4 bq = *(const float4*)&Wqs[kk][tx * 4];
            float4 bk = *(const float4*)&Wks[kk][tx * 4];
            float4 bv = *(const float4*)&Wvs[kk][tx * 4];
            #pragma unroll
            for (int i = 0; i < 4; i++) {
                aq[i][0] += xa[i] * bq.x; aq[i][1] += xa[i] * bq.y;
                aq[i][2] += xa[i] * bq.z; aq[i][3] += xa[i] * bq.w;
                ak[i][0] += xa[i] * bk.x; ak[i][1] += xa[i] * bk.y;
                ak[i][2] += xa[i] * bk.z; ak[i][3] += xa[i] * bk.w;
                av[i][0] += xa[i] * bv.x; av[i][1] += xa[i] * bv.y;
                av[i][2] += xa[i] * bv.z; av[i][3] += xa[i] * bv.w;
            }
        }
        __syncthreads();
    }

    const int b  = m0 / SS;
    const int s0 = m0 % SS;
    const size_t ob = ((size_t)(b * HH + h) * SS + s0) * DHD;
    #pragma unroll
    for (int i = 0; i < 4; i++) {
        size_t ro = ob + (size_t)(ty * 4 + i) * DHD + tx * 4;
        *(float4*)&g_q[ro] = make_float4(aq[i][0], aq[i][1], aq[i][2], aq[i][3]);
        *(float4*)&g_k[ro] = make_float4(ak[i][0], ak[i][1], ak[i][2], ak[i][3]);
        *(float4*)&g_v[ro] = make_float4(av[i][0], av[i][1], av[i][2], av[i][3]);
    }
}

// ---------------------------------------------------------------------------
// Flash attention with mma.sync m16n8k8 tf32.
// Block: 128 threads (4 warps). Q tile = 64 rows (16 per warp). K tiles = 64.
// K/V stored in smem pre-permuted into B-fragment order (tf32 bits) so each
// B-fragment is one conflict-free LDS.64. P stored per-warp in A-frag order.
// Online softmax in registers with quad shuffles.
// ---------------------------------------------------------------------------
__device__ __forceinline__ uint32_t f2tf(float x) {
    uint32_t r;
    asm("cvt.rna.tf32.f32 %0, %1;" : "=r"(r) : "f"(x));
    return r;
}

__device__ __forceinline__ void mma_tf32(float c[4], const uint32_t a[4],
                                         uint32_t b0, uint32_t b1) {
    asm volatile(
        "mma.sync.aligned.m16n8k8.row.col.f32.tf32.tf32.f32 "
        "{%0,%1,%2,%3}, {%4,%5,%6,%7}, {%8,%9}, {%0,%1,%2,%3};\n"
        : "+f"(c[0]), "+f"(c[1]), "+f"(c[2]), "+f"(c[3])
        : "r"(a[0]), "r"(a[1]), "r"(a[2]), "r"(a[3]), "r"(b0), "r"(b1));
}

#define ATT_SMEM_BYTES (12288 * 4)   // sK 4096 + sV 4096 + sP 4096 u32

__global__ __launch_bounds__(128, 2)
void flash_attn_tc_kernel(float* __restrict__ out) {
    extern __shared__ __align__(16) uint32_t smem_u[];
    uint32_t* sK = smem_u;            // [8 ktile][8 ntile][64]  B-frag order
    uint32_t* sV = smem_u + 4096;
    uint32_t* sP = smem_u + 8192;     // per-warp [8 ktile][128] A-frag order

    const int t    = threadIdx.x;
    const int w    = t >> 5;
    const int lane = t & 31;
    const int g    = lane >> 2;       // groupID 0..7
    const int lt   = lane & 3;        // thread-in-group 0..3

    const int bh = blockIdx.y;
    const int b  = bh / HH;
    const int h  = bh % HH;
    const int qi = blockIdx.x;
    const int q0 = qi * 64;

    const float* qp    = g_q + ((size_t)bh * SS + q0 + w * 16) * DHD;
    const float* kbase = g_k + (size_t)bh * SS * DHD;
    const float* vbase = g_v + (size_t)bh * SS * DHD;

    // Q fragments: 8 k-slabs x 4 regs, loaded once from gmem, tf32.
    uint32_t Qa[8][4];
    #pragma unroll
    for (int kk = 0; kk < 8; kk++) {
        int c = kk * 8 + lt;
        Qa[kk][0] = f2tf(qp[(size_t)g * DHD + c]);
        Qa[kk][1] = f2tf(qp[(size_t)(g + 8) * DHD + c]);
        Qa[kk][2] = f2tf(qp[(size_t)g * DHD + c + 4]);
        Qa[kk][3] = f2tf(qp[(size_t)(g + 8) * DHD + c + 4]);
    }

    // Online softmax state for rows (w*16+g) and (w*16+g+8), replicated per quad.
    float m0r = -INFINITY, m1r = -INFINITY;
    float l0r = 0.0f, l1r = 0.0f;
    float O[8][4];
    #pragma unroll
    for (int nt = 0; nt < 8; nt++)
        #pragma unroll
        for (int i = 0; i < 4; i++) O[nt][i] = 0.0f;

    const int r0 = q0 + w * 16 + g;      // global q row for c0/c1
    const int r1 = r0 + 8;               // for c2/c3
    uint32_t* sPw = sP + w * 1024;

    for (int j = 0; j <= qi; j++) {
        __syncthreads();
        // ---- load K/V tile (64x64 fp32) -> permuted tf32 smem ----
        const float* kp = kbase + (size_t)j * 64 * DHD;
        const float* vp = vbase + (size_t)j * 64 * DHD;
        #pragma unroll
        for (int i = 0; i < 8; i++) {
            int idx = t + i * 128;           // float4 index in 64x64 tile
            int row = idx >> 4;
            int c0  = (idx & 15) * 4;
            float4 kv = *(const float4*)&kp[(size_t)row * DHD + c0];
            float4 vv = *(const float4*)&vp[(size_t)row * DHD + c0];
            // K B-frag layout: tile=(e>>3)*8+(row>>3); off=(row&7)*8+((e>>2)&1)+ (e&3)*2
            int kb = ((c0 >> 3) * 8 + (row >> 3)) * 64 + (row & 7) * 8 + ((c0 >> 2) & 1);
            sK[kb + 0] = f2tf(kv.x);
            sK[kb + 2] = f2tf(kv.y);
            sK[kb + 4] = f2tf(kv.z);
            sK[kb + 6] = f2tf(kv.w);
            // V B-frag layout: tile=(row>>3)*8+(e>>3); off=(e&7)*8+(row&3)*2+((row>>2)&1)
            int vb = ((row >> 3) * 8 + (c0 >> 3)) * 64 + (c0 & 7) * 8
                     + (row & 3) * 2 + ((row >> 2) & 1);
            sV[vb + 0]  = f2tf(vv.x);
            sV[vb + 8]  = f2tf(vv.y);
            sV[vb + 16] = f2tf(vv.z);
            sV[vb + 24] = f2tf(vv.w);
        }
        __syncthreads();

        // ---- S = Q K^T : 8 n-tiles x 8 k-slabs ----
        float S[8][4];
        #pragma unroll
        for (int nt = 0; nt < 8; nt++)
            #pragma unroll
            for (int i = 0; i < 4; i++) S[nt][i] = 0.0f;
        #pragma unroll
        for (int kk = 0; kk < 8; kk++) {
            #pragma unroll
            for (int nt = 0; nt < 8; nt++) {
                uint2 bf = *(const uint2*)&sK[(kk * 8 + nt) * 64 + lane * 2];
                mma_tf32(S[nt], Qa[kk], bf.x, bf.y);
            }
        }

        // ---- scale + causal mask ----
        const float scale = 0.125f;
        const bool diag = (j == qi);
        #pragma unroll
        for (int nt = 0; nt < 8; nt++) {
            #pragma unroll
            for (int i = 0; i < 4; i++) S[nt][i] *= scale;
            if (diag) {
                int col = j * 64 + nt * 8 + 2 * lt;
                if (col     > r0) S[nt][0] = -INFINITY;
                if (col + 1 > r0) S[nt][1] = -INFINITY;
                if (col     > r1) S[nt][2] = -INFINITY;
                if (col + 1 > r1) S[nt][3] = -INFINITY;
            }
        }

        // ---- online softmax (registers + quad shuffles) ----
        float mx0 = -INFINITY, mx1 = -INFINITY;
        #pragma unroll
        for (int nt = 0; nt < 8; nt++) {
            mx0 = fmaxf(mx0, fmaxf(S[nt][0], S[nt][1]));
            mx1 = fmaxf(mx1, fmaxf(S[nt][2], S[nt][3]));
        }
        mx0 = fmaxf(mx0, __shfl_xor_sync(0xffffffffu, mx0, 1));
        mx0 = fmaxf(mx0, __shfl_xor_sync(0xffffffffu, mx0, 2));
        mx1 = fmaxf(mx1, __shfl_xor_sync(0xffffffffu, mx1, 1));
        mx1 = fmaxf(mx1, __shfl_xor_sync(0xffffffffu, mx1, 2));
        float mn0 = fmaxf(m0r, mx0);
        float mn1 = fmaxf(m1r, mx1);
        float f0 = __expf(m0r - mn0);     // 0 on first tile (m = -inf)
        float f1 = __expf(m1r - mn1);
        m0r = mn0; m1r = mn1;

        float ps0 = 0.0f, ps1 = 0.0f;
        #pragma unroll
        for (int nt = 0; nt < 8; nt++) {
            S[nt][0] = __expf(S[nt][0] - mn0);
            S[nt][1] = __expf(S[nt][1] - mn0);
            S[nt][2] = __expf(S[nt][2] - mn1);
            S[nt][3] = __expf(S[nt][3] - mn1);
            ps0 += S[nt][0] + S[nt][1];
            ps1 += S[nt][2] + S[nt][3];
        }
        ps0 += __shfl_xor_sync(0xffffffffu, ps0, 1);
        ps0 += __shfl_xor_sync(0xffffffffu, ps0, 2);
        ps1 += __shfl_xor_sync(0xffffffffu, ps1, 1);
        ps1 += __shfl_xor_sync(0xffffffffu, ps1, 2);
        l0r = l0r * f0 + ps0;
        l1r = l1r * f1 + ps1;

        // rescale O
        #pragma unroll
        for (int nt = 0; nt < 8; nt++) {
            O[nt][0] *= f0; O[nt][1] *= f0;
            O[nt][2] *= f1; O[nt][3] *= f1;
        }

        // ---- store P (tf32) into per-warp A-frag-ordered buffer ----
        // layout: kt*128 + rhi*64 + (rlo*4 + (c&3))*2 + ((c>>2)&1)
        #pragma unroll
        for (int nt = 0; nt < 8; nt++) {
            int c0 = 2 * lt, c1 = 2 * lt + 1;
            int lo0 = (g * 4 + (c0 & 3)) * 2 + ((c0 >> 2) & 1);
            int lo1 = (g * 4 + (c1 & 3)) * 2 + ((c1 >> 2) & 1);
            uint32_t* pb = sPw + nt * 128;
            pb[lo0]      = f2tf(S[nt][0]);
            pb[lo1]      = f2tf(S[nt][1]);
            pb[64 + lo0] = f2tf(S[nt][2]);
            pb[64 + lo1] = f2tf(S[nt][3]);
        }
        __syncwarp();

        // ---- O += P @ V : 8 k-slabs (kseq) x 8 n-tiles (e) ----
        #pragma unroll
        for (int kt = 0; kt < 8; kt++) {
            uint2 a02 = *(const uint2*)&sPw[kt * 128 + lane * 2];
            uint2 a13 = *(const uint2*)&sPw[kt * 128 + 64 + lane * 2];
            uint32_t A[4] = {a02.x, a13.x, a02.y, a13.y};
            #pragma unroll
            for (int nt = 0; nt < 8; nt++) {
                uint2 bf = *(const uint2*)&sV[(kt * 8 + nt) * 64 + lane * 2];
                mma_tf32(O[nt], A, bf.x, bf.y);
            }
        }
        __syncwarp();   // sPw reuse next iteration
    }

    // ---- write output: out[b][s][h*64+e] = O / l ----
    float inv0 = 1.0f / l0r;
    float inv1 = 1.0f / l1r;
    #pragma unroll
    for (int nt = 0; nt < 8; nt++) {
        int e = h * DHD + nt * 8 + 2 * lt;
        size_t o0 = ((size_t)b * SS + r0) * (HH * DHD) + e;
        size_t o1 = ((size_t)b * SS + r1) * (HH * DHD) + e;
        *(float2*)&out[o0] = make_float2(O[nt][0] * inv0, O[nt][1] * inv0);
        *(float2*)&out[o1] = make_float2(O[nt][2] * inv1, O[nt][3] * inv1);
    }
}

extern "C" void kernel_launch(void* const* d_in, const int* in_sizes, int n_in,
                              void* d_out, int out_size) {
    const float* x  = (const float*)d_in[0];
    const float* Wq = (const float*)d_in[1];
    const float* Wk = (const float*)d_in[2];
    const float* Wv = (const float*)d_in[3];
    float* out = (float*)d_out;

    cudaFuncSetAttribute(flash_attn_tc_kernel,
                         cudaFuncAttributeMaxDynamicSharedMemorySize,
                         ATT_SMEM_BYTES);

    qkv_proj_kernel<<<dim3(NROW / 64, HH), 256>>>(x, Wq, Wk, Wv);
    flash_attn_tc_kernel<<<dim3(SS / 64, BB * HH), 128, ATT_SMEM_BYTES>>>(out);
}

// round 3
// speedup vs baseline: 1.5758x; 1.1805x over previous
#include <cuda_runtime.h>
#include <math.h>
#include <stdint.h>

#define BB 2
#define SS 4096
#define DD 768
#define HH 12
#define DHD 64
#define NROW (BB*SS)

// Scratch for projected Q/K/V: [B,H,S,DH] each, fp32.
__device__ float g_q[(size_t)BB*HH*SS*DHD];
__device__ float g_k[(size_t)BB*HH*SS*DHD];
__device__ float g_v[(size_t)BB*HH*SS*DHD];

// ---------------------------------------------------------------------------
// QKV projection (unchanged): 64x64 tile per head, fp32 SIMT.
// ---------------------------------------------------------------------------
__global__ __launch_bounds__(256, 4)
void qkv_proj_kernel(const float* __restrict__ x,
                     const float* __restrict__ Wq,
                     const float* __restrict__ Wk,
                     const float* __restrict__ Wv) {
    const int BM = 64, BK = 32;
    __shared__ __align__(16) float Xs[BM][BK];
    __shared__ __align__(16) float Wqs[BK][DHD];
    __shared__ __align__(16) float Wks[BK][DHD];
    __shared__ __align__(16) float Wvs[BK][DHD];

    const int t  = threadIdx.x;
    const int h  = blockIdx.y;
    const int m0 = blockIdx.x * BM;
    const int ty = t >> 4;
    const int tx = t & 15;

    float aq[4][4] = {}, ak[4][4] = {}, av[4][4] = {};

    const float* wq = Wq + (size_t)h * DD * DHD;
    const float* wk = Wk + (size_t)h * DD * DHD;
    const float* wv = Wv + (size_t)h * DD * DHD;

    for (int k0 = 0; k0 < DD; k0 += BK) {
        #pragma unroll
        for (int i = 0; i < 2; i++) {
            int idx = t + i * 256;
            int row = idx >> 3;
            int col = (idx & 7) * 4;
            *(float4*)&Xs[row][col] =
                *(const float4*)&x[(size_t)(m0 + row) * DD + k0 + col];
        }
        #pragma unroll
        for (int i = 0; i < 2; i++) {
            int idx4 = (t + i * 256);
            const float4* sq = (const float4*)(wq + (size_t)k0 * DHD);
            const float4* sk = (const float4*)(wk + (size_t)k0 * DHD);
            const float4* sv = (const float4*)(wv + (size_t)k0 * DHD);
            ((float4*)&Wqs[0][0])[idx4] = sq[idx4];
            ((float4*)&Wks[0][0])[idx4] = sk[idx4];
            ((float4*)&Wvs[0][0])[idx4] = sv[idx4];
        }
        __syncthreads();

        #pragma unroll
        for (int kk = 0; kk < BK; kk++) {
            float xa[4];
            #pragma unroll
            for (int i = 0; i < 4; i++) xa[i] = Xs[ty * 4 + i][kk];
            float4 bq = *(const float4*)&Wqs[kk][tx * 4];
            float4 bk = *(const float4*)&Wks[kk][tx * 4];
            float4 bv = *(const float4*)&Wvs[kk][tx * 4];
            #pragma unroll
            for (int i = 0; i < 4; i++) {
                aq[i][0] += xa[i] * bq.x; aq[i][1] += xa[i] * bq.y;
                aq[i][2] += xa[i] * bq.z; aq[i][3] += xa[i] * bq.w;
                ak[i][0] += xa[i] * bk.x; ak[i][1] += xa[i] * bk.y;
                ak[i][2] += xa[i] * bk.z; ak[i][3] += xa[i] * bk.w;
                av[i][0] += xa[i] * bv.x; av[i][1] += xa[i] * bv.y;
                av[i][2] += xa[i] * bv.z; av[i][3] += xa[i] * bv.w;
            }
        }
        __syncthreads();
    }

    const int b  = m0 / SS;
    const int s0 = m0 % SS;
    const size_t ob = ((size_t)(b * HH + h) * SS + s0) * DHD;
    #pragma unroll
    for (int i = 0; i < 4; i++) {
        size_t ro = ob + (size_t)(ty * 4 + i) * DHD + tx * 4;
        *(float4*)&g_q[ro] = make_float4(aq[i][0], aq[i][1], aq[i][2], aq[i][3]);
        *(float4*)&g_k[ro] = make_float4(ak[i][0], ak[i][1], ak[i][2], ak[i][3]);
        *(float4*)&g_v[ro] = make_float4(av[i][0], av[i][1], av[i][2], av[i][3]);
    }
}

// ---------------------------------------------------------------------------
// Flash attention, mma.sync m16n8k8 tf32, conflict-free smem.
//  - K tile: row-major [64][68] tf32 (stride 68 -> B-frag LDS bank pattern
//    g*4+lt = 0..31, conflict-free; STS.128 staging conflict-free)
//  - V tile: row-major [64][72] tf32 (stride 72 -> lt*8+g = 0..31)
//  - P: stays in registers; A-fragments for P@V built with quad shuffles.
// Block 128 threads (4 warps x 16 q-rows), Q tile 64 rows.
// ---------------------------------------------------------------------------
__device__ __forceinline__ uint32_t f2tf(float x) {
    uint32_t r;
    asm("cvt.rna.tf32.f32 %0, %1;" : "=r"(r) : "f"(x));
    return r;
}

__device__ __forceinline__ void mma_tf32(float c[4], const uint32_t a[4],
                                         uint32_t b0, uint32_t b1) {
    asm volatile(
        "mma.sync.aligned.m16n8k8.row.col.f32.tf32.tf32.f32 "
        "{%0,%1,%2,%3}, {%4,%5,%6,%7}, {%8,%9}, {%0,%1,%2,%3};\n"
        : "+f"(c[0]), "+f"(c[1]), "+f"(c[2]), "+f"(c[3])
        : "r"(a[0]), "r"(a[1]), "r"(a[2]), "r"(a[3]), "r"(b0), "r"(b1));
}

#define KSTR 68
#define VSTR 72
#define ATT_SMEM_BYTES ((64 * KSTR + 64 * VSTR) * 4)

__global__ __launch_bounds__(128, 3)
void flash_attn_tc_kernel(float* __restrict__ out) {
    extern __shared__ __align__(16) uint32_t smem_u[];
    uint32_t* sK = smem_u;                 // [64][KSTR]
    uint32_t* sV = smem_u + 64 * KSTR;     // [64][VSTR]

    const int t    = threadIdx.x;
    const int w    = t >> 5;
    const int lane = t & 31;
    const int g    = lane >> 2;       // groupID 0..7
    const int lt   = lane & 3;        // thread-in-group 0..3

    const int bh = blockIdx.y;
    const int b  = bh / HH;
    const int h  = bh % HH;
    const int qi = blockIdx.x;
    const int q0 = qi * 64;

    const float* qp    = g_q + ((size_t)bh * SS + q0 + w * 16) * DHD;
    const float* kbase = g_k + (size_t)bh * SS * DHD;
    const float* vbase = g_v + (size_t)bh * SS * DHD;

    // Q fragments: 8 dh-slabs x 4 regs, loaded once, tf32.
    uint32_t Qa[8][4];
    #pragma unroll
    for (int kk = 0; kk < 8; kk++) {
        int c = kk * 8 + lt;
        Qa[kk][0] = f2tf(qp[(size_t)g * DHD + c]);
        Qa[kk][1] = f2tf(qp[(size_t)(g + 8) * DHD + c]);
        Qa[kk][2] = f2tf(qp[(size_t)g * DHD + c + 4]);
        Qa[kk][3] = f2tf(qp[(size_t)(g + 8) * DHD + c + 4]);
    }

    float m0r = -INFINITY, m1r = -INFINITY;
    float l0r = 0.0f, l1r = 0.0f;
    float O[8][4];
    #pragma unroll
    for (int nt = 0; nt < 8; nt++)
        #pragma unroll
        for (int i = 0; i < 4; i++) O[nt][i] = 0.0f;

    const int r0 = q0 + w * 16 + g;
    const int r1 = r0 + 8;

    const int srcA = (lane & 28) | (lt >> 1);
    const int srcB = srcA + 2;
    const int par  = lt & 1;

    for (int j = 0; j <= qi; j++) {
        __syncthreads();
        // ---- stage K/V tile: natural row-major, tf32, STS.128 ----
        const float* kp = kbase + (size_t)j * 64 * DHD;
        const float* vp = vbase + (size_t)j * 64 * DHD;
        #pragma unroll
        for (int i = 0; i < 8; i++) {
            int idx  = t + i * 128;          // float4 index in 64x64 tile
            int row  = idx >> 4;
            int col4 = (idx & 15) * 4;
            float4 kv = *(const float4*)&kp[(size_t)row * DHD + col4];
            float4 vv = *(const float4*)&vp[(size_t)row * DHD + col4];
            uint4 kt4 = make_uint4(f2tf(kv.x), f2tf(kv.y), f2tf(kv.z), f2tf(kv.w));
            uint4 vt4 = make_uint4(f2tf(vv.x), f2tf(vv.y), f2tf(vv.z), f2tf(vv.w));
            *(uint4*)&sK[row * KSTR + col4] = kt4;
            *(uint4*)&sV[row * VSTR + col4] = vt4;
        }
        __syncthreads();

        // ---- S = Q K^T ----
        // b0 = K[nt*8+g][kk*8+lt], b1 = K[nt*8+g][kk*8+lt+4]
        float S[8][4];
        #pragma unroll
        for (int nt = 0; nt < 8; nt++) {
            #pragma unroll
            for (int i = 0; i < 4; i++) S[nt][i] = 0.0f;
            const uint32_t* krow = &sK[(nt * 8 + g) * KSTR + lt];
            #pragma unroll
            for (int kk = 0; kk < 8; kk++) {
                uint32_t b0 = krow[kk * 8];
                uint32_t b1 = krow[kk * 8 + 4];
                mma_tf32(S[nt], Qa[kk], b0, b1);
            }
        }

        // ---- scale + causal mask ----
        const float scale = 0.125f;
        const bool diag = (j == qi);
        #pragma unroll
        for (int nt = 0; nt < 8; nt++) {
            #pragma unroll
            for (int i = 0; i < 4; i++) S[nt][i] *= scale;
            if (diag) {
                int col = j * 64 + nt * 8 + 2 * lt;
                if (col     > r0) S[nt][0] = -INFINITY;
                if (col + 1 > r0) S[nt][1] = -INFINITY;
                if (col     > r1) S[nt][2] = -INFINITY;
                if (col + 1 > r1) S[nt][3] = -INFINITY;
            }
        }

        // ---- online softmax (registers + quad shuffles) ----
        float mx0 = -INFINITY, mx1 = -INFINITY;
        #pragma unroll
        for (int nt = 0; nt < 8; nt++) {
            mx0 = fmaxf(mx0, fmaxf(S[nt][0], S[nt][1]));
            mx1 = fmaxf(mx1, fmaxf(S[nt][2], S[nt][3]));
        }
        mx0 = fmaxf(mx0, __shfl_xor_sync(0xffffffffu, mx0, 1));
        mx0 = fmaxf(mx0, __shfl_xor_sync(0xffffffffu, mx0, 2));
        mx1 = fmaxf(mx1, __shfl_xor_sync(0xffffffffu, mx1, 1));
        mx1 = fmaxf(mx1, __shfl_xor_sync(0xffffffffu, mx1, 2));
        float mn0 = fmaxf(m0r, mx0);
        float mn1 = fmaxf(m1r, mx1);
        float f0 = __expf(m0r - mn0);
        float f1 = __expf(m1r - mn1);
        m0r = mn0; m1r = mn1;

        float ps0 = 0.0f, ps1 = 0.0f;
        uint32_t Ptf[8][4];
        #pragma unroll
        for (int nt = 0; nt < 8; nt++) {
            float p0 = __expf(S[nt][0] - mn0);
            float p1 = __expf(S[nt][1] - mn0);
            float p2 = __expf(S[nt][2] - mn1);
            float p3 = __expf(S[nt][3] - mn1);
            ps0 += p0 + p1;
            ps1 += p2 + p3;
            Ptf[nt][0] = f2tf(p0); Ptf[nt][1] = f2tf(p1);
            Ptf[nt][2] = f2tf(p2); Ptf[nt][3] = f2tf(p3);
        }
        ps0 += __shfl_xor_sync(0xffffffffu, ps0, 1);
        ps0 += __shfl_xor_sync(0xffffffffu, ps0, 2);
        ps1 += __shfl_xor_sync(0xffffffffu, ps1, 1);
        ps1 += __shfl_xor_sync(0xffffffffu, ps1, 2);
        l0r = l0r * f0 + ps0;
        l1r = l1r * f1 + ps1;

        #pragma unroll
        for (int nt = 0; nt < 8; nt++) {
            O[nt][0] *= f0; O[nt][1] *= f0;
            O[nt][2] *= f1; O[nt][3] *= f1;
        }

        // ---- O += P @ V ----
        // A-frag for slab kt via quad shuffles:
        //   a0 = P[g][kt*8+lt]   (src lane (g, lt>>1), element parity lt&1)
        //   a2 = P[g][kt*8+lt+4] (src lane (g, (lt>>1)+2))
        #pragma unroll
        for (int kt = 0; kt < 8; kt++) {
            uint32_t pa0 = __shfl_sync(0xffffffffu, Ptf[kt][0], srcA);
            uint32_t pa1 = __shfl_sync(0xffffffffu, Ptf[kt][1], srcA);
            uint32_t pa2 = __shfl_sync(0xffffffffu, Ptf[kt][2], srcA);
            uint32_t pa3 = __shfl_sync(0xffffffffu, Ptf[kt][3], srcA);
            uint32_t pb0 = __shfl_sync(0xffffffffu, Ptf[kt][0], srcB);
            uint32_t pb1 = __shfl_sync(0xffffffffu, Ptf[kt][1], srcB);
            uint32_t pb2 = __shfl_sync(0xffffffffu, Ptf[kt][2], srcB);
            uint32_t pb3 = __shfl_sync(0xffffffffu, Ptf[kt][3], srcB);
            uint32_t A[4];
            A[0] = par ? pa1 : pa0;
            A[1] = par ? pa3 : pa2;
            A[2] = par ? pb1 : pb0;
            A[3] = par ? pb3 : pb2;
            const uint32_t* vrow0 = &sV[(kt * 8 + lt) * VSTR + g];
            const uint32_t* vrow1 = &sV[(kt * 8 + lt + 4) * VSTR + g];
            #pragma unroll
            for (int nt = 0; nt < 8; nt++) {
                uint32_t b0 = vrow0[nt * 8];
                uint32_t b1 = vrow1[nt * 8];
                mma_tf32(O[nt], A, b0, b1);
            }
        }
    }

    // ---- write output ----
    float inv0 = 1.0f / l0r;
    float inv1 = 1.0f / l1r;
    #pragma unroll
    for (int nt = 0; nt < 8; nt++) {
        int e = h * DHD + nt * 8 + 2 * lt;
        size_t o0 = ((size_t)b * SS + r0) * (HH * DHD) + e;
        size_t o1 = ((size_t)b * SS + r1) * (HH * DHD) + e;
        *(float2*)&out[o0] = make_float2(O[nt][0] * inv0, O[nt][1] * inv0);
        *(float2*)&out[o1] = make_float2(O[nt][2] * inv1, O[nt][3] * inv1);
    }
}

extern "C" void kernel_launch(void* const* d_in, const int* in_sizes, int n_in,
                              void* d_out, int out_size) {
    const float* x  = (const float*)d_in[0];
    const float* Wq = (const float*)d_in[1];
    const float* Wk = (const float*)d_in[2];
    const float* Wv = (const float*)d_in[3];
    float* out = (float*)d_out;

    cudaFuncSetAttribute(flash_attn_tc_kernel,
                         cudaFuncAttributeMaxDynamicSharedMemorySize,
                         ATT_SMEM_BYTES);

    qkv_proj_kernel<<<dim3(NROW / 64, HH), 256>>>(x, Wq, Wk, Wv);
    flash_attn_tc_kernel<<<dim3(SS / 64, BB * HH), 128, ATT_SMEM_BYTES>>>(out);
}

// round 4
// speedup vs baseline: 4.8931x; 3.1053x over previous
#include <cuda_runtime.h>
#include <math.h>
#include <stdint.h>

#define BB 2
#define SS 4096
#define DD 768
#define HH 12
#define DHD 64
#define NROW (BB*SS)

// Scratch for projected Q/K/V: [B,H,S,DH] each, fp32.
__device__ float g_q[(size_t)BB*HH*SS*DHD];
__device__ float g_k[(size_t)BB*HH*SS*DHD];
__device__ float g_v[(size_t)BB*HH*SS*DHD];

__device__ __forceinline__ uint32_t f2tf(float x) {
    uint32_t r;
    asm("cvt.rna.tf32.f32 %0, %1;" : "=r"(r) : "f"(x));
    return r;
}

__device__ __forceinline__ void mma_tf32(float c[4], const uint32_t a[4],
                                         uint32_t b0, uint32_t b1) {
    asm volatile(
        "mma.sync.aligned.m16n8k8.row.col.f32.tf32.tf32.f32 "
        "{%0,%1,%2,%3}, {%4,%5,%6,%7}, {%8,%9}, {%0,%1,%2,%3};\n"
        : "+f"(c[0]), "+f"(c[1]), "+f"(c[2]), "+f"(c[3])
        : "r"(a[0]), "r"(a[1]), "r"(a[2]), "r"(a[3]), "r"(b0), "r"(b1));
}

// ---------------------------------------------------------------------------
// QKV projection on the tensor pipe: 3xTF32 error-compensated mma.sync.
// Block 128 threads (4 warps). Warp w: rows m0+w*16..+15, all 3x64 cols.
// smem: X [64][36] fp32 (A-frag LDS bank = g*4+lt, conflict-free),
//       Wq/Wk/Wv [32][72] fp32 (B-frag LDS bank = lt*8+g, conflict-free).
// grid: (NROW/64, H)
// ---------------------------------------------------------------------------
#define XSTR 36
#define WSTR 72

__global__ __launch_bounds__(128)
void qkv_proj_tc_kernel(const float* __restrict__ x,
                        const float* __restrict__ Wq,
                        const float* __restrict__ Wk,
                        const float* __restrict__ Wv) {
    __shared__ __align__(16) float sX[64 * XSTR];
    __shared__ __align__(16) float sWq[32 * WSTR];
    __shared__ __align__(16) float sWk[32 * WSTR];
    __shared__ __align__(16) float sWv[32 * WSTR];

    const int t    = threadIdx.x;
    const int w    = t >> 5;
    const int lane = t & 31;
    const int g    = lane >> 2;
    const int lt   = lane & 3;

    const int h  = blockIdx.y;
    const int m0 = blockIdx.x * 64;

    const float* wqp = Wq + (size_t)h * DD * DHD;
    const float* wkp = Wk + (size_t)h * DD * DHD;
    const float* wvp = Wv + (size_t)h * DD * DHD;

    // acc[mat][ntile][4]
    float acc[3][8][4];
    #pragma unroll
    for (int m = 0; m < 3; m++)
        #pragma unroll
        for (int nt = 0; nt < 8; nt++)
            #pragma unroll
            for (int i = 0; i < 4; i++) acc[m][nt][i] = 0.0f;

    const int rA0 = (w * 16 + g) * XSTR;       // A rows g and g+8
    const int rA1 = (w * 16 + g + 8) * XSTR;

    for (int k0 = 0; k0 < DD; k0 += 32) {
        __syncthreads();
        // ---- stage X tile 64x32 ----
        #pragma unroll
        for (int i = 0; i < 4; i++) {
            int idx  = t + i * 128;            // 512 float4
            int row  = idx >> 3;               // 8 float4 per row
            int col4 = (idx & 7) * 4;
            *(float4*)&sX[row * XSTR + col4] =
                *(const float4*)&x[(size_t)(m0 + row) * DD + k0 + col4];
        }
        // ---- stage W tiles 32x64 (contiguous chunk of W[h]) ----
        #pragma unroll
        for (int i = 0; i < 4; i++) {
            int idx  = t + i * 128;            // 512 float4
            int row  = idx >> 4;               // 16 float4 per row
            int col4 = (idx & 15) * 4;
            size_t go = (size_t)(k0 + row) * DHD + col4;
            *(float4*)&sWq[row * WSTR + col4] = *(const float4*)&wqp[go];
            *(float4*)&sWk[row * WSTR + col4] = *(const float4*)&wkp[go];
            *(float4*)&sWv[row * WSTR + col4] = *(const float4*)&wvp[go];
        }
        __syncthreads();

        #pragma unroll 1
        for (int slab = 0; slab < 4; slab++) {
            // A fragments (rows w*16+g, +8; cols slab*8 + lt, +4), hi/lo split
            int ca = slab * 8 + lt;
            float x0 = sX[rA0 + ca];
            float x1 = sX[rA1 + ca];
            float x2 = sX[rA0 + ca + 4];
            float x3 = sX[rA1 + ca + 4];
            uint32_t Ah[4], Al[4];
            Ah[0] = f2tf(x0); Al[0] = f2tf(x0 - __uint_as_float(Ah[0]));
            Ah[1] = f2tf(x1); Al[1] = f2tf(x1 - __uint_as_float(Ah[1]));
            Ah[2] = f2tf(x2); Al[2] = f2tf(x2 - __uint_as_float(Ah[2]));
            Ah[3] = f2tf(x3); Al[3] = f2tf(x3 - __uint_as_float(Ah[3]));

            const int rb0 = (slab * 8 + lt) * WSTR + g;
            const int rb1 = (slab * 8 + lt + 4) * WSTR + g;
            #pragma unroll
            for (int nt = 0; nt < 8; nt++) {
                {   // Q
                    float b0f = sWq[rb0 + nt * 8];
                    float b1f = sWq[rb1 + nt * 8];
                    uint32_t bh0 = f2tf(b0f), bh1 = f2tf(b1f);
                    uint32_t bl0 = f2tf(b0f - __uint_as_float(bh0));
                    uint32_t bl1 = f2tf(b1f - __uint_as_float(bh1));
                    mma_tf32(acc[0][nt], Ah, bh0, bh1);
                    mma_tf32(acc[0][nt], Ah, bl0, bl1);
                    mma_tf32(acc[0][nt], Al, bh0, bh1);
                }
                {   // K
                    float b0f = sWk[rb0 + nt * 8];
                    float b1f = sWk[rb1 + nt * 8];
                    uint32_t bh0 = f2tf(b0f), bh1 = f2tf(b1f);
                    uint32_t bl0 = f2tf(b0f - __uint_as_float(bh0));
                    uint32_t bl1 = f2tf(b1f - __uint_as_float(bh1));
                    mma_tf32(acc[1][nt], Ah, bh0, bh1);
                    mma_tf32(acc[1][nt], Ah, bl0, bl1);
                    mma_tf32(acc[1][nt], Al, bh0, bh1);
                }
                {   // V
                    float b0f = sWv[rb0 + nt * 8];
                    float b1f = sWv[rb1 + nt * 8];
                    uint32_t bh0 = f2tf(b0f), bh1 = f2tf(b1f);
                    uint32_t bl0 = f2tf(b0f - __uint_as_float(bh0));
                    uint32_t bl1 = f2tf(b1f - __uint_as_float(bh1));
                    mma_tf32(acc[2][nt], Ah, bh0, bh1);
                    mma_tf32(acc[2][nt], Ah, bl0, bl1);
                    mma_tf32(acc[2][nt], Al, bh0, bh1);
                }
            }
        }
    }

    // ---- write out: rows m0 + w*16 + g (+8), cols nt*8 + 2*lt (+1) ----
    const int b  = m0 / SS;
    const int s0 = m0 % SS;
    const size_t ob = ((size_t)(b * HH + h) * SS + s0 + w * 16) * DHD;
    float* outs[3] = { g_q, g_k, g_v };
    #pragma unroll
    for (int m = 0; m < 3; m++) {
        float* op = outs[m] + ob;
        #pragma unroll
        for (int nt = 0; nt < 8; nt++) {
            int e = nt * 8 + 2 * lt;
            *(float2*)&op[(size_t)g * DHD + e] =
                make_float2(acc[m][nt][0], acc[m][nt][1]);
            *(float2*)&op[(size_t)(g + 8) * DHD + e] =
                make_float2(acc[m][nt][2], acc[m][nt][3]);
        }
    }
}

// ---------------------------------------------------------------------------
// Flash attention, mma.sync m16n8k8 tf32, conflict-free smem (R3) +
// reversed qi order for better tail scheduling.
// ---------------------------------------------------------------------------
#define KSTR 68
#define VSTR 72
#define ATT_SMEM_BYTES ((64 * KSTR + 64 * VSTR) * 4)

__global__ __launch_bounds__(128, 3)
void flash_attn_tc_kernel(float* __restrict__ out) {
    extern __shared__ __align__(16) uint32_t smem_u[];
    uint32_t* sK = smem_u;                 // [64][KSTR]
    uint32_t* sV = smem_u + 64 * KSTR;     // [64][VSTR]

    const int t    = threadIdx.x;
    const int w    = t >> 5;
    const int lane = t & 31;
    const int g    = lane >> 2;
    const int lt   = lane & 3;

    const int bh = blockIdx.y;
    const int b  = bh / HH;
    const int h  = bh % HH;
    const int qi = gridDim.x - 1 - blockIdx.x;   // heavy blocks first
    const int q0 = qi * 64;

    const float* qp    = g_q + ((size_t)bh * SS + q0 + w * 16) * DHD;
    const float* kbase = g_k + (size_t)bh * SS * DHD;
    const float* vbase = g_v + (size_t)bh * SS * DHD;

    uint32_t Qa[8][4];
    #pragma unroll
    for (int kk = 0; kk < 8; kk++) {
        int c = kk * 8 + lt;
        Qa[kk][0] = f2tf(qp[(size_t)g * DHD + c]);
        Qa[kk][1] = f2tf(qp[(size_t)(g + 8) * DHD + c]);
        Qa[kk][2] = f2tf(qp[(size_t)g * DHD + c + 4]);
        Qa[kk][3] = f2tf(qp[(size_t)(g + 8) * DHD + c + 4]);
    }

    float m0r = -INFINITY, m1r = -INFINITY;
    float l0r = 0.0f, l1r = 0.0f;
    float O[8][4];
    #pragma unroll
    for (int nt = 0; nt < 8; nt++)
        #pragma unroll
        for (int i = 0; i < 4; i++) O[nt][i] = 0.0f;

    const int r0 = q0 + w * 16 + g;
    const int r1 = r0 + 8;

    const int srcA = (lane & 28) | (lt >> 1);
    const int srcB = srcA + 2;
    const int par  = lt & 1;

    for (int j = 0; j <= qi; j++) {
        __syncthreads();
        const float* kp = kbase + (size_t)j * 64 * DHD;
        const float* vp = vbase + (size_t)j * 64 * DHD;
        #pragma unroll
        for (int i = 0; i < 8; i++) {
            int idx  = t + i * 128;
            int row  = idx >> 4;
            int col4 = (idx & 15) * 4;
            float4 kv = *(const float4*)&kp[(size_t)row * DHD + col4];
            float4 vv = *(const float4*)&vp[(size_t)row * DHD + col4];
            uint4 kt4 = make_uint4(f2tf(kv.x), f2tf(kv.y), f2tf(kv.z), f2tf(kv.w));
            uint4 vt4 = make_uint4(f2tf(vv.x), f2tf(vv.y), f2tf(vv.z), f2tf(vv.w));
            *(uint4*)&sK[row * KSTR + col4] = kt4;
            *(uint4*)&sV[row * VSTR + col4] = vt4;
        }
        __syncthreads();

        float S[8][4];
        #pragma unroll
        for (int nt = 0; nt < 8; nt++) {
            #pragma unroll
            for (int i = 0; i < 4; i++) S[nt][i] = 0.0f;
            const uint32_t* krow = &sK[(nt * 8 + g) * KSTR + lt];
            #pragma unroll
            for (int kk = 0; kk < 8; kk++) {
                uint32_t b0 = krow[kk * 8];
                uint32_t b1 = krow[kk * 8 + 4];
                mma_tf32(S[nt], Qa[kk], b0, b1);
            }
        }

        const float scale = 0.125f;
        const bool diag = (j == qi);
        #pragma unroll
        for (int nt = 0; nt < 8; nt++) {
            #pragma unroll
            for (int i = 0; i < 4; i++) S[nt][i] *= scale;
            if (diag) {
                int col = j * 64 + nt * 8 + 2 * lt;
                if (col     > r0) S[nt][0] = -INFINITY;
                if (col + 1 > r0) S[nt][1] = -INFINITY;
                if (col     > r1) S[nt][2] = -INFINITY;
                if (col + 1 > r1) S[nt][3] = -INFINITY;
            }
        }

        float mx0 = -INFINITY, mx1 = -INFINITY;
        #pragma unroll
        for (int nt = 0; nt < 8; nt++) {
            mx0 = fmaxf(mx0, fmaxf(S[nt][0], S[nt][1]));
            mx1 = fmaxf(mx1, fmaxf(S[nt][2], S[nt][3]));
        }
        mx0 = fmaxf(mx0, __shfl_xor_sync(0xffffffffu, mx0, 1));
        mx0 = fmaxf(mx0, __shfl_xor_sync(0xffffffffu, mx0, 2));
        mx1 = fmaxf(mx1, __shfl_xor_sync(0xffffffffu, mx1, 1));
        mx1 = fmaxf(mx1, __shfl_xor_sync(0xffffffffu, mx1, 2));
        float mn0 = fmaxf(m0r, mx0);
        float mn1 = fmaxf(m1r, mx1);
        float f0 = __expf(m0r - mn0);
        float f1 = __expf(m1r - mn1);
        m0r = mn0; m1r = mn1;

        float ps0 = 0.0f, ps1 = 0.0f;
        uint32_t Ptf[8][4];
        #pragma unroll
        for (int nt = 0; nt < 8; nt++) {
            float p0 = __expf(S[nt][0] - mn0);
            float p1 = __expf(S[nt][1] - mn0);
            float p2 = __expf(S[nt][2] - mn1);
            float p3 = __expf(S[nt][3] - mn1);
            ps0 += p0 + p1;
            ps1 += p2 + p3;
            Ptf[nt][0] = f2tf(p0); Ptf[nt][1] = f2tf(p1);
            Ptf[nt][2] = f2tf(p2); Ptf[nt][3] = f2tf(p3);
        }
        ps0 += __shfl_xor_sync(0xffffffffu, ps0, 1);
        ps0 += __shfl_xor_sync(0xffffffffu, ps0, 2);
        ps1 += __shfl_xor_sync(0xffffffffu, ps1, 1);
        ps1 += __shfl_xor_sync(0xffffffffu, ps1, 2);
        l0r = l0r * f0 + ps0;
        l1r = l1r * f1 + ps1;

        #pragma unroll
        for (int nt = 0; nt < 8; nt++) {
            O[nt][0] *= f0; O[nt][1] *= f0;
            O[nt][2] *= f1; O[nt][3] *= f1;
        }

        #pragma unroll
        for (int kt = 0; kt < 8; kt++) {
            uint32_t pa0 = __shfl_sync(0xffffffffu, Ptf[kt][0], srcA);
            uint32_t pa1 = __shfl_sync(0xffffffffu, Ptf[kt][1], srcA);
            uint32_t pa2 = __shfl_sync(0xffffffffu, Ptf[kt][2], srcA);
            uint32_t pa3 = __shfl_sync(0xffffffffu, Ptf[kt][3], srcA);
            uint32_t pb0 = __shfl_sync(0xffffffffu, Ptf[kt][0], srcB);
            uint32_t pb1 = __shfl_sync(0xffffffffu, Ptf[kt][1], srcB);
            uint32_t pb2 = __shfl_sync(0xffffffffu, Ptf[kt][2], srcB);
            uint32_t pb3 = __shfl_sync(0xffffffffu, Ptf[kt][3], srcB);
            uint32_t A[4];
            A[0] = par ? pa1 : pa0;
            A[1] = par ? pa3 : pa2;
            A[2] = par ? pb1 : pb0;
            A[3] = par ? pb3 : pb2;
            const uint32_t* vrow0 = &sV[(kt * 8 + lt) * VSTR + g];
            const uint32_t* vrow1 = &sV[(kt * 8 + lt + 4) * VSTR + g];
            #pragma unroll
            for (int nt = 0; nt < 8; nt++) {
                uint32_t b0 = vrow0[nt * 8];
                uint32_t b1 = vrow1[nt * 8];
                mma_tf32(O[nt], A, b0, b1);
            }
        }
    }

    float inv0 = 1.0f / l0r;
    float inv1 = 1.0f / l1r;
    #pragma unroll
    for (int nt = 0; nt < 8; nt++) {
        int e = h * DHD + nt * 8 + 2 * lt;
        size_t o0 = ((size_t)b * SS + r0) * (HH * DHD) + e;
        size_t o1 = ((size_t)b * SS + r1) * (HH * DHD) + e;
        *(float2*)&out[o0] = make_float2(O[nt][0] * inv0, O[nt][1] * inv0);
        *(float2*)&out[o1] = make_float2(O[nt][2] * inv1, O[nt][3] * inv1);
    }
}

extern "C" void kernel_launch(void* const* d_in, const int* in_sizes, int n_in,
                              void* d_out, int out_size) {
    const float* x  = (const float*)d_in[0];
    const float* Wq = (const float*)d_in[1];
    const float* Wk = (const float*)d_in[2];
    const float* Wv = (const float*)d_in[3];
    float* out = (float*)d_out;

    cudaFuncSetAttribute(flash_attn_tc_kernel,
                         cudaFuncAttributeMaxDynamicSharedMemorySize,
                         ATT_SMEM_BYTES);

    qkv_proj_tc_kernel<<<dim3(NROW / 64, HH), 128>>>(x, Wq, Wk, Wv);
    flash_attn_tc_kernel<<<dim3(SS / 64, BB * HH), 128, ATT_SMEM_BYTES>>>(out);
}

// round 9
// speedup vs baseline: 4.9460x; 1.0108x over previous
#include <cuda_runtime.h>
#include <math.h>
#include <stdint.h>

#define BB 2
#define SS 4096
#define DD 768
#define HH 12
#define DHD 64
#define NROW (BB*SS)

// Scratch for projected Q/K/V: [B,H,S,DH] each, fp32.
__device__ float g_q[(size_t)BB*HH*SS*DHD];
__device__ float g_k[(size_t)BB*HH*SS*DHD];
__device__ float g_v[(size_t)BB*HH*SS*DHD];

__device__ __forceinline__ uint32_t f2tf(float x) {
    uint32_t r;
    asm("cvt.rna.tf32.f32 %0, %1;" : "=r"(r) : "f"(x));
    return r;
}

__device__ __forceinline__ void mma_tf32(float c[4], const uint32_t a[4],
                                         uint32_t b0, uint32_t b1) {
    asm volatile(
        "mma.sync.aligned.m16n8k8.row.col.f32.tf32.tf32.f32 "
        "{%0,%1,%2,%3}, {%4,%5,%6,%7}, {%8,%9}, {%0,%1,%2,%3};\n"
        : "+f"(c[0]), "+f"(c[1]), "+f"(c[2]), "+f"(c[3])
        : "r"(a[0]), "r"(a[1]), "r"(a[2]), "r"(a[3]), "r"(b0), "r"(b1));
}

// ---------------------------------------------------------------------------
// QKV projection on the tensor pipe (unchanged from R4): 3xTF32 split mma.
// ---------------------------------------------------------------------------
#define XSTR 36
#define WSTR 72

__global__ __launch_bounds__(128)
void qkv_proj_tc_kernel(const float* __restrict__ x,
                        const float* __restrict__ Wq,
                        const float* __restrict__ Wk,
                        const float* __restrict__ Wv) {
    __shared__ __align__(16) float sX[64 * XSTR];
    __shared__ __align__(16) float sWq[32 * WSTR];
    __shared__ __align__(16) float sWk[32 * WSTR];
    __shared__ __align__(16) float sWv[32 * WSTR];

    const int t    = threadIdx.x;
    const int w    = t >> 5;
    const int lane = t & 31;
    const int g    = lane >> 2;
    const int lt   = lane & 3;

    const int h  = blockIdx.y;
    const int m0 = blockIdx.x * 64;

    const float* wqp = Wq + (size_t)h * DD * DHD;
    const float* wkp = Wk + (size_t)h * DD * DHD;
    const float* wvp = Wv + (size_t)h * DD * DHD;

    float acc[3][8][4];
    #pragma unroll
    for (int m = 0; m < 3; m++)
        #pragma unroll
        for (int nt = 0; nt < 8; nt++)
            #pragma unroll
            for (int i = 0; i < 4; i++) acc[m][nt][i] = 0.0f;

    const int rA0 = (w * 16 + g) * XSTR;
    const int rA1 = (w * 16 + g + 8) * XSTR;

    for (int k0 = 0; k0 < DD; k0 += 32) {
        __syncthreads();
        #pragma unroll
        for (int i = 0; i < 4; i++) {
            int idx  = t + i * 128;
            int row  = idx >> 3;
            int col4 = (idx & 7) * 4;
            *(float4*)&sX[row * XSTR + col4] =
                *(const float4*)&x[(size_t)(m0 + row) * DD + k0 + col4];
        }
        #pragma unroll
        for (int i = 0; i < 4; i++) {
            int idx  = t + i * 128;
            int row  = idx >> 4;
            int col4 = (idx & 15) * 4;
            size_t go = (size_t)(k0 + row) * DHD + col4;
            *(float4*)&sWq[row * WSTR + col4] = *(const float4*)&wqp[go];
            *(float4*)&sWk[row * WSTR + col4] = *(const float4*)&wkp[go];
            *(float4*)&sWv[row * WSTR + col4] = *(const float4*)&wvp[go];
        }
        __syncthreads();

        #pragma unroll 1
        for (int slab = 0; slab < 4; slab++) {
            int ca = slab * 8 + lt;
            float x0 = sX[rA0 + ca];
            float x1 = sX[rA1 + ca];
            float x2 = sX[rA0 + ca + 4];
            float x3 = sX[rA1 + ca + 4];
            uint32_t Ah[4], Al[4];
            Ah[0] = f2tf(x0); Al[0] = f2tf(x0 - __uint_as_float(Ah[0]));
            Ah[1] = f2tf(x1); Al[1] = f2tf(x1 - __uint_as_float(Ah[1]));
            Ah[2] = f2tf(x2); Al[2] = f2tf(x2 - __uint_as_float(Ah[2]));
            Ah[3] = f2tf(x3); Al[3] = f2tf(x3 - __uint_as_float(Ah[3]));

            const int rb0 = (slab * 8 + lt) * WSTR + g;
            const int rb1 = (slab * 8 + lt + 4) * WSTR + g;
            #pragma unroll
            for (int nt = 0; nt < 8; nt++) {
                {
                    float b0f = sWq[rb0 + nt * 8];
                    float b1f = sWq[rb1 + nt * 8];
                    uint32_t bh0 = f2tf(b0f), bh1 = f2tf(b1f);
                    uint32_t bl0 = f2tf(b0f - __uint_as_float(bh0));
                    uint32_t bl1 = f2tf(b1f - __uint_as_float(bh1));
                    mma_tf32(acc[0][nt], Ah, bh0, bh1);
                    mma_tf32(acc[0][nt], Ah, bl0, bl1);
                    mma_tf32(acc[0][nt], Al, bh0, bh1);
                }
                {
                    float b0f = sWk[rb0 + nt * 8];
                    float b1f = sWk[rb1 + nt * 8];
                    uint32_t bh0 = f2tf(b0f), bh1 = f2tf(b1f);
                    uint32_t bl0 = f2tf(b0f - __uint_as_float(bh0));
                    uint32_t bl1 = f2tf(b1f - __uint_as_float(bh1));
                    mma_tf32(acc[1][nt], Ah, bh0, bh1);
                    mma_tf32(acc[1][nt], Ah, bl0, bl1);
                    mma_tf32(acc[1][nt], Al, bh0, bh1);
                }
                {
                    float b0f = sWv[rb0 + nt * 8];
                    float b1f = sWv[rb1 + nt * 8];
                    uint32_t bh0 = f2tf(b0f), bh1 = f2tf(b1f);
                    uint32_t bl0 = f2tf(b0f - __uint_as_float(bh0));
                    uint32_t bl1 = f2tf(b1f - __uint_as_float(bh1));
                    mma_tf32(acc[2][nt], Ah, bh0, bh1);
                    mma_tf32(acc[2][nt], Ah, bl0, bl1);
                    mma_tf32(acc[2][nt], Al, bh0, bh1);
                }
            }
        }
    }

    const int b  = m0 / SS;
    const int s0 = m0 % SS;
    const size_t ob = ((size_t)(b * HH + h) * SS + s0 + w * 16) * DHD;
    float* outs[3] = { g_q, g_k, g_v };
    #pragma unroll
    for (int m = 0; m < 3; m++) {
        float* op = outs[m] + ob;
        #pragma unroll
        for (int nt = 0; nt < 8; nt++) {
            int e = nt * 8 + 2 * lt;
            *(float2*)&op[(size_t)g * DHD + e] =
                make_float2(acc[m][nt][0], acc[m][nt][1]);
            *(float2*)&op[(size_t)(g + 8) * DHD + e] =
                make_float2(acc[m][nt][2], acc[m][nt][3]);
        }
    }
}

// ---------------------------------------------------------------------------
// Flash attention, mma.sync tf32, M=32 per warp (Q tile 128 rows, 4 warps).
// Every K/V B-fragment load now feeds 2 MMAs -> 1.0 LDS.32 per MMA.
// ---------------------------------------------------------------------------
#define KSTR 68
#define VSTR 72
#define ATT_SMEM_BYTES ((64 * KSTR + 64 * VSTR) * 4)

__global__ __launch_bounds__(128, 2)
void flash_attn_tc_kernel(float* __restrict__ out) {
    extern __shared__ __align__(16) uint32_t smem_u[];
    uint32_t* sK = smem_u;                 // [64][KSTR]
    uint32_t* sV = smem_u + 64 * KSTR;     // [64][VSTR]

    const int t    = threadIdx.x;
    const int w    = t >> 5;
    const int lane = t & 31;
    const int g    = lane >> 2;
    const int lt   = lane & 3;

    const int bh = blockIdx.y;
    const int b  = bh / HH;
    const int h  = bh % HH;
    const int qi = gridDim.x - 1 - blockIdx.x;   // heavy blocks first
    const int q0 = qi * 128;

    const float* qp    = g_q + ((size_t)bh * SS + q0 + w * 32) * DHD;
    const float* kbase = g_k + (size_t)bh * SS * DHD;
    const float* vbase = g_v + (size_t)bh * SS * DHD;

    // Q fragments: 2 m-tiles x 8 dh-slabs x 4 regs, loaded once, tf32.
    uint32_t Qa[2][8][4];
    #pragma unroll
    for (int u = 0; u < 2; u++) {
        #pragma unroll
        for (int kk = 0; kk < 8; kk++) {
            int c = kk * 8 + lt;
            Qa[u][kk][0] = f2tf(qp[(size_t)(u * 16 + g) * DHD + c]);
            Qa[u][kk][1] = f2tf(qp[(size_t)(u * 16 + g + 8) * DHD + c]);
            Qa[u][kk][2] = f2tf(qp[(size_t)(u * 16 + g) * DHD + c + 4]);
            Qa[u][kk][3] = f2tf(qp[(size_t)(u * 16 + g + 8) * DHD + c + 4]);
        }
    }

    float mr[2][2], lr[2][2];
    #pragma unroll
    for (int u = 0; u < 2; u++) {
        mr[u][0] = -INFINITY; mr[u][1] = -INFINITY;
        lr[u][0] = 0.0f;      lr[u][1] = 0.0f;
    }
    float O[2][8][4];
    #pragma unroll
    for (int u = 0; u < 2; u++)
        #pragma unroll
        for (int nt = 0; nt < 8; nt++)
            #pragma unroll
            for (int i = 0; i < 4; i++) O[u][nt][i] = 0.0f;

    const int srcA = (lane & 28) | (lt >> 1);
    const int srcB = srcA + 2;
    const int par  = lt & 1;

    const int jmax = 2 * qi + 1;
    for (int j = 0; j <= jmax; j++) {
        __syncthreads();
        // ---- stage K/V tile (64x64), tf32, STS.128, conflict-free ----
        const float* kp = kbase + (size_t)j * 64 * DHD;
        const float* vp = vbase + (size_t)j * 64 * DHD;
        #pragma unroll
        for (int i = 0; i < 8; i++) {
            int idx  = t + i * 128;
            int row  = idx >> 4;
            int col4 = (idx & 15) * 4;
            float4 kv = *(const float4*)&kp[(size_t)row * DHD + col4];
            float4 vv = *(const float4*)&vp[(size_t)row * DHD + col4];
            uint4 kt4 = make_uint4(f2tf(kv.x), f2tf(kv.y), f2tf(kv.z), f2tf(kv.w));
            uint4 vt4 = make_uint4(f2tf(vv.x), f2tf(vv.y), f2tf(vv.z), f2tf(vv.w));
            *(uint4*)&sK[row * KSTR + col4] = kt4;
            *(uint4*)&sV[row * VSTR + col4] = vt4;
        }
        __syncthreads();

        // ---- S = Q K^T : each B-fragment feeds both m-tiles ----
        float S[2][8][4];
        #pragma unroll
        for (int u = 0; u < 2; u++)
            #pragma unroll
            for (int nt = 0; nt < 8; nt++)
                #pragma unroll
                for (int i = 0; i < 4; i++) S[u][nt][i] = 0.0f;
        #pragma unroll
        for (int kk = 0; kk < 8; kk++) {
            #pragma unroll
            for (int nt = 0; nt < 8; nt++) {
                const uint32_t* krow = &sK[(nt * 8 + g) * KSTR + kk * 8 + lt];
                uint32_t b0 = krow[0];
                uint32_t b1 = krow[4];
                mma_tf32(S[0][nt], Qa[0][kk], b0, b1);
                mma_tf32(S[1][nt], Qa[1][kk], b0, b1);
            }
        }

        // ---- scale + causal mask + online softmax per m-tile ----
        const float scale = 0.125f;
        uint32_t Ptf[2][8][4];
        #pragma unroll
        for (int u = 0; u < 2; u++) {
            const int r0 = q0 + w * 32 + u * 16 + g;
            const int r1 = r0 + 8;
            #pragma unroll
            for (int nt = 0; nt < 8; nt++) {
                #pragma unroll
                for (int i = 0; i < 4; i++) S[u][nt][i] *= scale;
            }
            if (j * 64 + 63 > q0 + w * 32 + u * 16) {
                #pragma unroll
                for (int nt = 0; nt < 8; nt++) {
                    int col = j * 64 + nt * 8 + 2 * lt;
                    if (col     > r0) S[u][nt][0] = -INFINITY;
                    if (col + 1 > r0) S[u][nt][1] = -INFINITY;
                    if (col     > r1) S[u][nt][2] = -INFINITY;
                    if (col + 1 > r1) S[u][nt][3] = -INFINITY;
                }
            }

            float mx0 = -INFINITY, mx1 = -INFINITY;
            #pragma unroll
            for (int nt = 0; nt < 8; nt++) {
                mx0 = fmaxf(mx0, fmaxf(S[u][nt][0], S[u][nt][1]));
                mx1 = fmaxf(mx1, fmaxf(S[u][nt][2], S[u][nt][3]));
            }
            mx0 = fmaxf(mx0, __shfl_xor_sync(0xffffffffu, mx0, 1));
            mx0 = fmaxf(mx0, __shfl_xor_sync(0xffffffffu, mx0, 2));
            mx1 = fmaxf(mx1, __shfl_xor_sync(0xffffffffu, mx1, 1));
            mx1 = fmaxf(mx1, __shfl_xor_sync(0xffffffffu, mx1, 2));
            float mn0 = fmaxf(mr[u][0], mx0);
            float mn1 = fmaxf(mr[u][1], mx1);
            float f0 = __expf(mr[u][0] - mn0);
            float f1 = __expf(mr[u][1] - mn1);
            mr[u][0] = mn0; mr[u][1] = mn1;

            float ps0 = 0.0f, ps1 = 0.0f;
            #pragma unroll
            for (int nt = 0; nt < 8; nt++) {
                float p0 = __expf(S[u][nt][0] - mn0);
                float p1 = __expf(S[u][nt][1] - mn0);
                float p2 = __expf(S[u][nt][2] - mn1);
                float p3 = __expf(S[u][nt][3] - mn1);
                ps0 += p0 + p1;
                ps1 += p2 + p3;
                Ptf[u][nt][0] = f2tf(p0); Ptf[u][nt][1] = f2tf(p1);
                Ptf[u][nt][2] = f2tf(p2); Ptf[u][nt][3] = f2tf(p3);
            }
            ps0 += __shfl_xor_sync(0xffffffffu, ps0, 1);
            ps0 += __shfl_xor_sync(0xffffffffu, ps0, 2);
            ps1 += __shfl_xor_sync(0xffffffffu, ps1, 1);
            ps1 += __shfl_xor_sync(0xffffffffu, ps1, 2);
            lr[u][0] = lr[u][0] * f0 + ps0;
            lr[u][1] = lr[u][1] * f1 + ps1;

            #pragma unroll
            for (int nt = 0; nt < 8; nt++) {
                O[u][nt][0] *= f0; O[u][nt][1] *= f0;
                O[u][nt][2] *= f1; O[u][nt][3] *= f1;
            }
        }

        // ---- O += P @ V : each V B-fragment feeds both m-tiles ----
        #pragma unroll
        for (int kt = 0; kt < 8; kt++) {
            uint32_t A[2][4];
            #pragma unroll
            for (int u = 0; u < 2; u++) {
                uint32_t pa0 = __shfl_sync(0xffffffffu, Ptf[u][kt][0], srcA);
                uint32_t pa1 = __shfl_sync(0xffffffffu, Ptf[u][kt][1], srcA);
                uint32_t pa2 = __shfl_sync(0xffffffffu, Ptf[u][kt][2], srcA);
                uint32_t pa3 = __shfl_sync(0xffffffffu, Ptf[u][kt][3], srcA);
                uint32_t pb0 = __shfl_sync(0xffffffffu, Ptf[u][kt][0], srcB);
                uint32_t pb1 = __shfl_sync(0xffffffffu, Ptf[u][kt][1], srcB);
                uint32_t pb2 = __shfl_sync(0xffffffffu, Ptf[u][kt][2], srcB);
                uint32_t pb3 = __shfl_sync(0xffffffffu, Ptf[u][kt][3], srcB);
                A[u][0] = par ? pa1 : pa0;
                A[u][1] = par ? pa3 : pa2;
                A[u][2] = par ? pb1 : pb0;
                A[u][3] = par ? pb3 : pb2;
            }
            const uint32_t* vrow0 = &sV[(kt * 8 + lt) * VSTR + g];
            const uint32_t* vrow1 = &sV[(kt * 8 + lt + 4) * VSTR + g];
            #pragma unroll
            for (int nt = 0; nt < 8; nt++) {
                uint32_t b0 = vrow0[nt * 8];
                uint32_t b1 = vrow1[nt * 8];
                mma_tf32(O[0][nt], A[0], b0, b1);
                mma_tf32(O[1][nt], A[1], b0, b1);
            }
        }
    }

    // ---- write output ----
    #pragma unroll
    for (int u = 0; u < 2; u++) {
        const int r0 = q0 + w * 32 + u * 16 + g;
        const int r1 = r0 + 8;
        float inv0 = 1.0f / lr[u][0];
        float inv1 = 1.0f / lr[u][1];
        #pragma unroll
        for (int nt = 0; nt < 8; nt++) {
            int e = h * DHD + nt * 8 + 2 * lt;
            size_t o0 = ((size_t)b * SS + r0) * (HH * DHD) + e;
            size_t o1 = ((size_t)b * SS + r1) * (HH * DHD) + e;
            *(float2*)&out[o0] = make_float2(O[u][nt][0] * inv0, O[u][nt][1] * inv0);
            *(float2*)&out[o1] = make_float2(O[u][nt][2] * inv1, O[u][nt][3] * inv1);
        }
    }
}

extern "C" void kernel_launch(void* const* d_in, const int* in_sizes, int n_in,
                              void* d_out, int out_size) {
    const float* x  = (const float*)d_in[0];
    const float* Wq = (const float*)d_in[1];
    const float* Wk = (const float*)d_in[2];
    const float* Wv = (const float*)d_in[3];
    float* out = (float*)d_out;

    cudaFuncSetAttribute(flash_attn_tc_kernel,
                         cudaFuncAttributeMaxDynamicSharedMemorySize,
                         ATT_SMEM_BYTES);

    qkv_proj_tc_kernel<<<dim3(NROW / 64, HH), 128>>>(x, Wq, Wk, Wv);
    flash_attn_tc_kernel<<<dim3(SS / 128, BB * HH), 128, ATT_SMEM_BYTES>>>(out);
}